// round 16
// baseline (speedup 1.0000x reference)
#include <cuda_runtime.h>
#include <cuda_fp16.h>
#include <cmath>

// Problem constants
#define Bq     2
#define Sq     2048
#define Dm     1024
#define NQ     16
#define NKV    4
#define GRP    4
#define DQh    64
#define DVh    64

// exp(s*0.125) = exp2(s * C)
#define EXP2C  0.180336879f

// Scratch (device globals — no allocation allowed)
__device__ __align__(16) __half g_xnq[Bq*Sq*Dm];
__device__ __align__(16) __half g_xnk[Bq*Sq*Dm];
__device__ __align__(16) __half g_xnv[Bq*Sq*Dm];
__device__ __align__(16) __half g_Wqh[Dm*NQ*DQh];
__device__ __align__(16) __half g_Wkh[Dm*NKV*DQh];
__device__ __align__(16) __half g_Wvh[Dm*NKV*DVh];
__device__ __align__(16) __half g_Woh[NQ*DVh*Dm];
__device__ __align__(16) __half g_Qh[Bq*Sq*NQ*DQh];
__device__ __align__(16) __half g_Kh[Bq*Sq*NKV*DQh];
__device__ __align__(16) __half g_Vh[Bq*Sq*NKV*DVh];
__device__ __align__(16) __half g_Oh[Bq*Sq*NQ*DVh];

// fp16 mma: m16n8k16, f32 accum
#define MMA_F16(c, a, b0, b1)                                                  \
    asm volatile("mma.sync.aligned.m16n8k16.row.col.f32.f16.f16.f32 "          \
                 "{%0,%1,%2,%3},{%4,%5,%6,%7},{%8,%9},{%0,%1,%2,%3};"          \
                 : "+f"((c)[0]), "+f"((c)[1]), "+f"((c)[2]), "+f"((c)[3])      \
                 : "r"((a)[0]), "r"((a)[1]), "r"((a)[2]), "r"((a)[3]),         \
                   "r"(b0), "r"(b1))

__device__ __forceinline__ void ldsmx4(unsigned r[4], unsigned saddr) {
    asm volatile("ldmatrix.sync.aligned.m8n8.x4.shared.b16 {%0,%1,%2,%3}, [%4];"
                 : "=r"(r[0]), "=r"(r[1]), "=r"(r[2]), "=r"(r[3])
                 : "r"(saddr));
}
__device__ __forceinline__ void ldsmx4t(unsigned r[4], unsigned saddr) {
    asm volatile("ldmatrix.sync.aligned.m8n8.x4.trans.shared.b16 {%0,%1,%2,%3}, [%4];"
                 : "=r"(r[0]), "=r"(r[1]), "=r"(r[2]), "=r"(r[3])
                 : "r"(saddr));
}

__device__ __forceinline__ unsigned a_frag_addr(const __half* base, int lane,
                                                int r0, int ldm) {
    const __half* p = base + (size_t)(r0 + (lane & 7) + ((lane >> 3) & 1) * 8) * ldm
                           + ((lane >> 4) & 1) * 8;
    return (unsigned)__cvta_generic_to_shared(p);
}
__device__ __forceinline__ unsigned bn_frag_addr(const __half* base, int lane,
                                                 int n0, int ldm) {
    const __half* p = base + (size_t)(n0 + (lane & 7) + ((lane >> 4) & 1) * 8) * ldm
                           + ((lane >> 3) & 1) * 8;
    return (unsigned)__cvta_generic_to_shared(p);
}
__device__ __forceinline__ unsigned bt_frag_addr(const __half* base, int lane,
                                                 int k0, int n0, int ldm) {
    const __half* p = base + (size_t)(k0 + (lane & 7) + ((lane >> 3) & 1) * 8) * ldm
                           + n0 + ((lane >> 4) & 1) * 8;
    return (unsigned)__cvta_generic_to_shared(p);
}

__device__ __forceinline__ void cpasync16(unsigned dst, const void* src) {
    asm volatile("cp.async.cg.shared.global [%0], [%1], 16;" :: "r"(dst), "l"(src));
}
#define CP_COMMIT() asm volatile("cp.async.commit_group;")
#define CP_WAIT0()  asm volatile("cp.async.wait_group 0;")
#define CP_WAIT1()  asm volatile("cp.async.wait_group 1;")

__device__ __forceinline__ __half2 f22h(float a, float b) {
    return __floats2half2_rn(a, b);
}
__device__ __forceinline__ unsigned pack_h2(float a, float b) {
    __half2 h = __floats2half2_rn(a, b);
    return *(unsigned*)&h;
}

// ---------------------------------------------------------------------------
// Static causal upper-triangle zero-fill (independent; runs on side stream)
// ---------------------------------------------------------------------------
__global__ void zfill_kernel(float* __restrict__ attn)
{
    int idx = blockIdx.x;                 // 0..511
    int h = idx >> 4, mt = idx & 15;
    int c0 = 128 * (mt + 1);
    int w4 = (Sq - c0) >> 2;
    if (w4 <= 0) return;
    float4 z = make_float4(0.f, 0.f, 0.f, 0.f);
    size_t rowbase = ((size_t)h * Sq + mt * 128) * Sq + c0;
    for (int r = 0; r < 128; r++) {
        float4* rp = (float4*)(attn + rowbase + (size_t)r * Sq);
        for (int c4 = threadIdx.x; c4 < w4; c4 += 256)
            rp[c4] = z;
    }
}

// ---------------------------------------------------------------------------
// Fused LayerNorm x3 + weight fp32->fp16 conversion (one launch).
// ---------------------------------------------------------------------------
__global__ void ln3w_kernel(const float* __restrict__ xq,
                            const float* __restrict__ xk,
                            const float* __restrict__ xv,
                            const float* __restrict__ gamma,
                            const float* __restrict__ beta,
                            __half* __restrict__ yq,
                            __half* __restrict__ yk,
                            __half* __restrict__ yv,
                            const float* __restrict__ Wq, const float* __restrict__ Wo,
                            const float* __restrict__ Wk, const float* __restrict__ Wv,
                            __half* wq, __half* wo, __half* wk, __half* wv)
{
    int which = blockIdx.y;
    int tid = threadIdx.x;
    if (which >= 3) {
        int w = which - 3;
        const float* src = (w == 0) ? Wq : (w == 1) ? Wo : (w == 2) ? Wk : Wv;
        __half* dst      = (w == 0) ? wq : (w == 1) ? wo : (w == 2) ? wk : wv;
        int n = (w < 2) ? Dm * Dm : Dm * NKV * DQh;
        int i = (blockIdx.x * 256 + tid) * 4;
        if (i < n) {
            float4 v = *(const float4*)&src[i];
            *(__half2*)&dst[i]     = f22h(v.x, v.y);
            *(__half2*)&dst[i + 2] = f22h(v.z, v.w);
        }
        return;
    }
    int row = blockIdx.x;
    const float* x = (which == 0) ? xq : (which == 1) ? xk : xv;
    __half* y      = (which == 0) ? yq : (which == 1) ? yk : yv;
    const float4* xr = (const float4*)(x + (size_t)row * Dm);
    float4 v = xr[tid];
    float s  = v.x + v.y + v.z + v.w;
    float ss = v.x*v.x + v.y*v.y + v.z*v.z + v.w*v.w;
    #pragma unroll
    for (int o = 16; o > 0; o >>= 1) {
        s  += __shfl_down_sync(0xffffffffu, s,  o);
        ss += __shfl_down_sync(0xffffffffu, ss, o);
    }
    __shared__ float as[8], bs[8];
    __shared__ float s_mu, s_inv;
    if ((tid & 31) == 0) { as[tid >> 5] = s; bs[tid >> 5] = ss; }
    __syncthreads();
    if (tid == 0) {
        float S = 0.f, SS = 0.f;
        #pragma unroll
        for (int i = 0; i < 8; i++) { S += as[i]; SS += bs[i]; }
        float mu  = S * (1.0f / Dm);
        float var = SS * (1.0f / Dm) - mu * mu;
        s_mu  = mu;
        s_inv = rsqrtf(var + 1e-5f);
    }
    __syncthreads();
    float mu = s_mu, inv = s_inv;
    float4 g  = ((const float4*)gamma)[tid];
    float4 bb = ((const float4*)beta )[tid];
    int base = row * Dm + tid * 4;
    *(__half2*)&y[base]     = f22h((v.x - mu) * inv * g.x + bb.x,
                                   (v.y - mu) * inv * g.y + bb.y);
    *(__half2*)&y[base + 2] = f22h((v.z - mu) * inv * g.z + bb.z,
                                   (v.w - mu) * inv * g.w + bb.w);
}

// ---------------------------------------------------------------------------
// fp16 GEMM with bias: 128x128 block, BK=32, 8 warps of 64x32, 3-stage
// cp.async pipeline, 2 CTAs/SM. Optional fused RoPE in epilogue.
// ---------------------------------------------------------------------------
#define G_ALD 40
#define G_BLD 136
#define G_AS (128*G_ALD)
#define G_BS (32*G_BLD)
#define GEMM_SMEM (3*(G_AS + G_BS)*2)

__device__ __forceinline__ void gemm_body(const __half* __restrict__ A,
                                          const __half* __restrict__ B,
                                          const float* __restrict__ bias,
                                          float* __restrict__ Cf,
                                          __half* __restrict__ Ch,
                                          int N, int K,
                                          int mblk, int nblk,
                                          bool do_rope,
                                          __half* smem)
{
    __half* As = smem;                   // [3][128][40]
    __half* Bs = smem + 3 * G_AS;        // [3][32][136]

    int tid  = threadIdx.x;
    int lane = tid & 31, wid = tid >> 5;
    int wm = (wid & 1) * 64, wn = (wid >> 1) * 32;
    int l4 = lane >> 2, lk = lane & 3;
    int mb = mblk * 128, nb = nblk * 128;

    unsigned as_base = (unsigned)__cvta_generic_to_shared(As);
    unsigned bs_base = (unsigned)__cvta_generic_to_shared(Bs);

    int ar = tid >> 1, ach = (tid & 1) * 2;
    const __half* Ap = A + (size_t)(mb + ar) * K + ach * 8;

    float c[4][4][4];
    #pragma unroll
    for (int mi = 0; mi < 4; mi++)
        #pragma unroll
        for (int nj = 0; nj < 4; nj++)
            #pragma unroll
            for (int q = 0; q < 4; q++) c[mi][nj][q] = 0.f;

    #define G_LOAD(T, BUF)                                                     \
        do {                                                                   \
            cpasync16(as_base + (unsigned)((BUF) * G_AS + ar * G_ALD + ach * 8) * 2, \
                      Ap + (size_t)(T) * 32);                                  \
            cpasync16(as_base + (unsigned)((BUF) * G_AS + ar * G_ALD + ach * 8 + 8) * 2, \
                      Ap + (size_t)(T) * 32 + 8);                              \
            _Pragma("unroll")                                                  \
            for (int u_ = 0; u_ < 2; u_++) {                                   \
                int lin_ = tid + u_ * 256;                                     \
                int kr_ = lin_ >> 4, ch_ = lin_ & 15;                          \
                cpasync16(bs_base + (unsigned)((BUF) * G_BS + kr_ * G_BLD + ch_ * 8) * 2, \
                          B + (size_t)((T) * 32 + kr_) * N + nb + ch_ * 8);    \
            }                                                                  \
        } while (0)

    int nt = K >> 5;
    G_LOAD(0, 0); CP_COMMIT();
    if (nt > 1) { G_LOAD(1, 1); CP_COMMIT(); }

    for (int t = 0; t < nt; t++) {
        int cur = t % 3;
        if (t + 1 < nt) { CP_WAIT1(); } else { CP_WAIT0(); }
        __syncthreads();
        if (t + 2 < nt) { G_LOAD(t + 2, (t + 2) % 3); CP_COMMIT(); }

        const __half* Ab = As + cur * G_AS;
        const __half* Bb = Bs + cur * G_BS;

        #pragma unroll
        for (int kk = 0; kk < 2; kk++) {
            unsigned af[4][4];
            #pragma unroll
            for (int mi = 0; mi < 4; mi++)
                ldsmx4(af[mi], a_frag_addr(Ab, lane, wm + mi * 16, G_ALD) + kk * 32);
            #pragma unroll
            for (int g = 0; g < 2; g++) {
                unsigned bfr[4];
                ldsmx4t(bfr, bt_frag_addr(Bb, lane, kk * 16, wn + g * 16, G_BLD));
                #pragma unroll
                for (int mi = 0; mi < 4; mi++) {
                    MMA_F16(c[mi][2*g],   af[mi], bfr[0], bfr[1]);
                    MMA_F16(c[mi][2*g+1], af[mi], bfr[2], bfr[3]);
                }
            }
        }
    }
    #undef G_LOAD

    #pragma unroll
    for (int nj = 0; nj < 4; nj++) {
        int col = nb + wn + nj * 8 + 2 * lk;
        float2 bj = *(const float2*)&bias[col];
        float invf = 0.f;
        if (do_rope) {
            int pi = (col & 63) >> 1;
            invf = exp2f(-0.4152410118609203f * (float)pi);
        }
        #pragma unroll
        for (int mi = 0; mi < 4; mi++) {
            int r0 = mb + wm + mi * 16 + l4;
            float v0 = c[mi][nj][0] + bj.x, v1 = c[mi][nj][1] + bj.y;
            float v2 = c[mi][nj][2] + bj.x, v3 = c[mi][nj][3] + bj.y;
            if (do_rope) {
                int t0 = r0 & (Sq - 1);
                float sn0, cs0, sn1, cs1;
                sincosf((float)t0 * invf, &sn0, &cs0);
                sincosf((float)(t0 + 8) * invf, &sn1, &cs1);
                float a0 = v0, b0 = v1;
                v0 = a0 * cs0 - b0 * sn0; v1 = a0 * sn0 + b0 * cs0;
                float a1 = v2, b1 = v3;
                v2 = a1 * cs1 - b1 * sn1; v3 = a1 * sn1 + b1 * cs1;
            }
            if (Ch) {
                *(__half2*)&Ch[(size_t)r0 * N + col] = f22h(v0, v1);
                *(__half2*)&Ch[(size_t)(r0 + 8) * N + col] = f22h(v2, v3);
            } else {
                float2 o0; o0.x = v0; o0.y = v1;
                float2 o1; o1.x = v2; o1.y = v3;
                *(float2*)&Cf[(size_t)r0 * N + col] = o0;
                *(float2*)&Cf[(size_t)(r0 + 8) * N + col] = o1;
            }
        }
    }
}

// Fused Q+K+V projections (384 GEMM CTAs, rope fused)
__global__ void __launch_bounds__(256, 2)
gemm_qkv(const __half* __restrict__ Aq, const __half* __restrict__ Ak,
         const __half* __restrict__ Av,
         const __half* __restrict__ Wq, const __half* __restrict__ Wk,
         const __half* __restrict__ Wv,
         const float* __restrict__ bq_, const float* __restrict__ bk_,
         const float* __restrict__ bv_,
         __half* __restrict__ Cq, __half* __restrict__ Ck,
         __half* __restrict__ Cv)
{
    extern __shared__ __half smh[];
    int bx = blockIdx.x;
    if (bx < 256) {
        gemm_body(Aq, Wq, bq_, nullptr, Cq, NQ * DQh, Dm, bx >> 3, bx & 7, true, smh);
    } else if (bx < 320) {
        int i = bx - 256;
        gemm_body(Ak, Wk, bk_, nullptr, Ck, NKV * DQh, Dm, i >> 1, i & 1, true, smh);
    } else {
        int i = bx - 320;
        gemm_body(Av, Wv, bv_, nullptr, Cv, NKV * DVh, Dm, i >> 1, i & 1, false, smh);
    }
}

// Output projection: 256 CTAs
__global__ void __launch_bounds__(256, 2)
gemm_o(const __half* __restrict__ A, const __half* __restrict__ B,
       const float* __restrict__ bias, float* __restrict__ Cf)
{
    extern __shared__ __half smh[];
    int bx = blockIdx.x;
    gemm_body(A, B, bias, Cf, nullptr, Dm, Dm, bx >> 3, bx & 7, false, smh);
}

// ---------------------------------------------------------------------------
// Attention: FA2 layout, 128-wide key tiles in two halves, 2 CTAs/SM,
// complementary q-tile pairs, m-hat=0 softmax, Q frags in registers,
// sweep-1 K triple-buffered.
// ---------------------------------------------------------------------------
#define A_LD 72
#define A_TS (128*A_LD)
#define ATTN_SMEM (5*A_TS*2)
#define KSTEP_B (16*A_LD*2)

__global__ void __launch_bounds__(256, 2)
attn_kernel(const int* __restrict__ lens, float* __restrict__ attn)
{
    extern __shared__ __half smh[];
    __half* Qs  = smh;
    __half* Ks0 = Qs + A_TS;
    __half* Ks1 = Ks0 + A_TS;
    __half* Vs0 = Ks1 + A_TS;          // sweep 1: third K buffer
    __half* Vs1 = Vs0 + A_TS;

    int tid  = threadIdx.x;
    int lane = tid & 31, wid = tid >> 5;
    int wm = wid * 16;
    int l4 = lane >> 2, lk = lane & 3;

    int bx = blockIdx.x;                 // 0..7
    int qh = blockIdx.y, b = blockIdx.z;
    int kvh = qh >> 2;
    int grp = qh & 3;
    int len = lens[b];

    unsigned qs_addr = (unsigned)__cvta_generic_to_shared(Qs);
    unsigned ks_addr3[3] = {
        (unsigned)__cvta_generic_to_shared(Ks0),
        (unsigned)__cvta_generic_to_shared(Ks1),
        (unsigned)__cvta_generic_to_shared(Vs0)
    };
    unsigned vs_addr[2] = {
        (unsigned)__cvta_generic_to_shared(Vs0),
        (unsigned)__cvta_generic_to_shared(Vs1)
    };

    unsigned q_ptr = a_frag_addr(Qs, lane, wm, A_LD);
    unsigned k_base3[3] = { bn_frag_addr(Ks0, lane, 0, A_LD),
                            bn_frag_addr(Ks1, lane, 0, A_LD),
                            bn_frag_addr(Vs0, lane, 0, A_LD) };
    unsigned v_base[2] = { bt_frag_addr(Vs0, lane, 0, 0, A_LD),
                           bt_frag_addr(Vs1, lane, 0, 0, A_LD) };

    size_t attn_head = (((size_t)(b * GRP + grp)) * NKV + kvh) * Sq;

    #define LOAD_K_ASYNC(JT, BUFADDR)                                           \
        do {                                                                    \
            _Pragma("unroll")                                                   \
            for (int i_ = 0; i_ < 4; i_++) {                                    \
                int lin_ = tid + i_ * 256;                                      \
                int r_ = lin_ >> 3, ch_ = lin_ & 7;                             \
                cpasync16((BUFADDR) + (unsigned)(r_ * A_LD + ch_ * 8) * 2,      \
                    &g_Kh[((size_t)(b * Sq + (JT) * 128 + r_)) * (NKV * DQh)    \
                          + kvh * 64 + ch_ * 8]);                               \
            }                                                                   \
        } while (0)
    #define LOAD_V_ASYNC(JT, BUFADDR)                                           \
        do {                                                                    \
            _Pragma("unroll")                                                   \
            for (int i_ = 0; i_ < 4; i_++) {                                    \
                int lin_ = tid + i_ * 256;                                      \
                int r_ = lin_ >> 3, ch_ = lin_ & 7;                             \
                cpasync16((BUFADDR) + (unsigned)(r_ * A_LD + ch_ * 8) * 2,      \
                    &g_Vh[((size_t)(b * Sq + (JT) * 128 + r_)) * (NKV * DQh)    \
                          + kvh * 64 + ch_ * 8]);                               \
            }                                                                   \
        } while (0)

    #define QK_HALF(KB, H)                                                      \
        do {                                                                    \
            _Pragma("unroll")                                                   \
            for (int kk = 0; kk < 4; kk++) {                                    \
                _Pragma("unroll")                                               \
                for (int g2 = 0; g2 < 4; g2++) {                                \
                    unsigned bfr[4];                                            \
                    ldsmx4(bfr, (KB) + ((H) * 4 + g2) * KSTEP_B + kk * 32);     \
                    MMA_F16(s[2*g2],   qf[kk], bfr[0], bfr[1]);                 \
                    MMA_F16(s[2*g2+1], qf[kk], bfr[2], bfr[3]);                 \
                }                                                               \
            }                                                                   \
        } while (0)

    #pragma unroll 1
    for (int hp = 0; hp < 2; hp++) {
        int mt = hp ? bx : (Sq / 128 - 1 - bx);   // heavy tile first
        __syncthreads();

        int jend = min(mt, (len - 1) >> 7);

        #pragma unroll
        for (int i = 0; i < 4; i++) {
            int lin = tid + i * 256;
            int r = lin >> 3, ch = lin & 7;
            cpasync16(qs_addr + (unsigned)(r * A_LD + ch * 8) * 2,
                      &g_Qh[((size_t)(b * Sq + mt * 128 + r)) * (NQ * DQh) + qh * 64 + ch * 8]);
        }
        LOAD_K_ASYNC(0, ks_addr3[0]);
        CP_COMMIT();
        if (jend >= 1) { LOAD_K_ASYNC(1, ks_addr3[1]); CP_COMMIT(); }

        float rl0 = 0.f, rl1 = 0.f;
        int qr0 = mt * 128 + wm + l4, qr1 = qr0 + 8;

        if (jend >= 1) { CP_WAIT1(); } else { CP_WAIT0(); }
        __syncthreads();
        unsigned qf[4][4];
        #pragma unroll
        for (int kk = 0; kk < 4; kk++)
            ldsmx4(qf[kk], q_ptr + kk * 32);

        // =================== Sweep 1: l only (m-hat = 0), K 3-stage =========
        for (int jt = 0; jt <= jend; jt++) {
            int kb = jt % 3;
            if (jt > 0) {
                if (jt < jend) { CP_WAIT1(); } else { CP_WAIT0(); }
                __syncthreads();
            }
            if (jt + 2 <= jend) { LOAD_K_ASYNC(jt + 2, ks_addr3[(jt + 2) % 3]); CP_COMMIT(); }
            bool boundary = (jt == jend);

            float s0 = 0.f, s1 = 0.f;
            #pragma unroll
            for (int H = 0; H < 2; H++) {
                float s[8][4];
                #pragma unroll
                for (int nj = 0; nj < 8; nj++)
                    #pragma unroll
                    for (int q = 0; q < 4; q++) s[nj][q] = 0.f;
                QK_HALF(k_base3[kb], H);

                if (boundary) {
                    #pragma unroll
                    for (int nj = 0; nj < 8; nj++) {
                        int kc0 = jt * 128 + H * 64 + nj * 8 + 2 * lk, kc1 = kc0 + 1;
                        s0 += ((kc0 > qr0 || kc0 >= len) ? 0.f : exp2f(s[nj][0] * EXP2C))
                            + ((kc1 > qr0 || kc1 >= len) ? 0.f : exp2f(s[nj][1] * EXP2C));
                        s1 += ((kc0 > qr1 || kc0 >= len) ? 0.f : exp2f(s[nj][2] * EXP2C))
                            + ((kc1 > qr1 || kc1 >= len) ? 0.f : exp2f(s[nj][3] * EXP2C));
                    }
                } else {
                    #pragma unroll
                    for (int nj = 0; nj < 8; nj++) {
                        s0 += exp2f(s[nj][0] * EXP2C) + exp2f(s[nj][1] * EXP2C);
                        s1 += exp2f(s[nj][2] * EXP2C) + exp2f(s[nj][3] * EXP2C);
                    }
                }
            }
            s0 += __shfl_xor_sync(0xffffffffu, s0, 1);
            s0 += __shfl_xor_sync(0xffffffffu, s0, 2);
            s1 += __shfl_xor_sync(0xffffffffu, s1, 1);
            s1 += __shfl_xor_sync(0xffffffffu, s1, 2);
            rl0 += s0;
            rl1 += s1;
        }
        __syncthreads();

        float il0 = 1.0f / rl0, il1 = 1.0f / rl1;

        float o[8][4];
        #pragma unroll
        for (int dj = 0; dj < 8; dj++)
            #pragma unroll
            for (int q = 0; q < 4; q++) o[dj][q] = 0.f;

        // =================== Sweep 2: probs + PV ============================
        LOAD_K_ASYNC(0, ks_addr3[0]);
        LOAD_V_ASYNC(0, vs_addr[0]);
        CP_COMMIT();
        for (int jt = 0; jt <= jend; jt++) {
            CP_WAIT0();
            __syncthreads();
            int kb = jt & 1;
            if (jt < jend) {
                LOAD_K_ASYNC(jt + 1, ks_addr3[kb ^ 1]);
                LOAD_V_ASYNC(jt + 1, vs_addr[kb ^ 1]);
                CP_COMMIT();
            }
            bool boundary = (jt == jend);

            #pragma unroll
            for (int H = 0; H < 2; H++) {
                float s[8][4];
                #pragma unroll
                for (int nj = 0; nj < 8; nj++)
                    #pragma unroll
                    for (int q = 0; q < 4; q++) s[nj][q] = 0.f;
                QK_HALF(k_base3[kb], H);

                if (boundary) {
                    #pragma unroll
                    for (int nj = 0; nj < 8; nj++) {
                        int kc0 = jt * 128 + H * 64 + nj * 8 + 2 * lk, kc1 = kc0 + 1;
                        s[nj][0] = (kc0 > qr0 || kc0 >= len) ? 0.f
                                 : exp2f(s[nj][0] * EXP2C) * il0;
                        s[nj][1] = (kc1 > qr0 || kc1 >= len) ? 0.f
                                 : exp2f(s[nj][1] * EXP2C) * il0;
                        s[nj][2] = (kc0 > qr1 || kc0 >= len) ? 0.f
                                 : exp2f(s[nj][2] * EXP2C) * il1;
                        s[nj][3] = (kc1 > qr1 || kc1 >= len) ? 0.f
                                 : exp2f(s[nj][3] * EXP2C) * il1;
                    }
                } else {
                    #pragma unroll
                    for (int nj = 0; nj < 8; nj++) {
                        s[nj][0] = exp2f(s[nj][0] * EXP2C) * il0;
                        s[nj][1] = exp2f(s[nj][1] * EXP2C) * il0;
                        s[nj][2] = exp2f(s[nj][2] * EXP2C) * il1;
                        s[nj][3] = exp2f(s[nj][3] * EXP2C) * il1;
                    }
                }

                #pragma unroll
                for (int kk = 0; kk < 4; kk++) {
                    unsigned af[4];
                    af[0] = pack_h2(s[2*kk][0],   s[2*kk][1]);
                    af[1] = pack_h2(s[2*kk][2],   s[2*kk][3]);
                    af[2] = pack_h2(s[2*kk+1][0], s[2*kk+1][1]);
                    af[3] = pack_h2(s[2*kk+1][2], s[2*kk+1][3]);
                    #pragma unroll
                    for (int g = 0; g < 4; g++) {
                        unsigned bfr[4];
                        ldsmx4t(bfr, v_base[kb] + g * 32 + (H * 4 + kk) * KSTEP_B);
                        MMA_F16(o[2*g],   af, bfr[0], bfr[1]);
                        MMA_F16(o[2*g+1], af, bfr[2], bfr[3]);
                    }
                }

                #pragma unroll
                for (int nj = 0; nj < 8; nj++) {
                    int kc0 = jt * 128 + H * 64 + nj * 8 + 2 * lk;
                    float2 w0; w0.x = s[nj][0]; w0.y = s[nj][1];
                    float2 w1; w1.x = s[nj][2]; w1.y = s[nj][3];
                    *(float2*)&attn[(attn_head + qr0) * Sq + kc0] = w0;
                    *(float2*)&attn[(attn_head + qr1) * Sq + kc0] = w1;
                }
            }
        }

        // zero-fill dynamic masked band (jend+1 .. mt); static jt > mt on s2.
        for (int jt = jend + 1; jt <= mt; jt++) {
            float4 z = make_float4(0.f, 0.f, 0.f, 0.f);
            #pragma unroll
            for (int i = 0; i < 16; i++) {
                int lin = tid + i * 256;
                int r = lin >> 5, c4 = (lin & 31) * 4;
                *(float4*)&attn[(attn_head + mt * 128 + r) * Sq + jt * 128 + c4] = z;
            }
        }

        // epilogue: write O (fp16)
        {
            int gr0 = b * Sq + qr0;
            #pragma unroll
            for (int dj = 0; dj < 8; dj++) {
                int col = qh * 64 + dj * 8 + 2 * lk;
                *(__half2*)&g_Oh[(size_t)gr0 * (NQ * DVh) + col] = f22h(o[dj][0], o[dj][1]);
                *(__half2*)&g_Oh[(size_t)(gr0 + 8) * (NQ * DVh) + col] = f22h(o[dj][2], o[dj][3]);
            }
        }
    }
    #undef LOAD_K_ASYNC
    #undef LOAD_V_ASYNC
    #undef QK_HALF
}

// ---------------------------------------------------------------------------
// Launch (fork/join: static zero-fill overlaps the whole main chain)
// ---------------------------------------------------------------------------
extern "C" void kernel_launch(void* const* d_in, const int* in_sizes, int n_in,
                              void* d_out, int out_size)
{
    const float* x_q  = (const float*)d_in[0];
    const float* x_k  = (const float*)d_in[1];
    const float* x_v  = (const float*)d_in[2];
    const int*   lens = (const int*)  d_in[3];
    const float* gam  = (const float*)d_in[4];
    const float* bet  = (const float*)d_in[5];
    const float* Wq   = (const float*)d_in[6];
    const float* bq   = (const float*)d_in[7];
    const float* Wk   = (const float*)d_in[8];
    const float* bk   = (const float*)d_in[9];
    const float* Wv   = (const float*)d_in[10];
    const float* bv   = (const float*)d_in[11];
    const float* Wo   = (const float*)d_in[12];
    const float* bo   = (const float*)d_in[13];

    float* out  = (float*)d_out;                       // (B, S, 1024)
    float* attn = out + (size_t)Bq * Sq * Dm;          // (B, GRP, NKV, S, S)

    __half *xnq, *xnk, *xnv, *Qh, *Kh, *Vh, *Oh;
    __half *Wqh, *Wkh, *Wvh, *Woh;
    cudaGetSymbolAddress((void**)&xnq, g_xnq);
    cudaGetSymbolAddress((void**)&xnk, g_xnk);
    cudaGetSymbolAddress((void**)&xnv, g_xnv);
    cudaGetSymbolAddress((void**)&Qh,  g_Qh);
    cudaGetSymbolAddress((void**)&Kh,  g_Kh);
    cudaGetSymbolAddress((void**)&Vh,  g_Vh);
    cudaGetSymbolAddress((void**)&Oh,  g_Oh);
    cudaGetSymbolAddress((void**)&Wqh, g_Wqh);
    cudaGetSymbolAddress((void**)&Wkh, g_Wkh);
    cudaGetSymbolAddress((void**)&Wvh, g_Wvh);
    cudaGetSymbolAddress((void**)&Woh, g_Woh);

    const int M = Bq * Sq;   // 4096

    static cudaStream_t s2 = nullptr;
    static cudaEvent_t ev_fork = nullptr, ev_join = nullptr;
    static bool init_done = false;
    if (!init_done) {
        cudaFuncSetAttribute(gemm_qkv, cudaFuncAttributeMaxDynamicSharedMemorySize, GEMM_SMEM);
        cudaFuncSetAttribute(gemm_o, cudaFuncAttributeMaxDynamicSharedMemorySize, GEMM_SMEM);
        cudaFuncSetAttribute(attn_kernel, cudaFuncAttributeMaxDynamicSharedMemorySize, ATTN_SMEM);
        cudaStreamCreateWithFlags(&s2, cudaStreamNonBlocking);
        cudaEventCreateWithFlags(&ev_fork, cudaEventDisableTiming);
        cudaEventCreateWithFlags(&ev_join, cudaEventDisableTiming);
        init_done = true;
    }

    // fork: static zero-fill on side stream (no data dependencies)
    cudaEventRecord(ev_fork, 0);
    cudaStreamWaitEvent(s2, ev_fork, 0);
    zfill_kernel<<<512, 256, 0, s2>>>(attn);
    cudaEventRecord(ev_join, s2);

    // main chain
    ln3w_kernel<<<dim3(M, 7), 256>>>(x_q, x_k, x_v, gam, bet, xnq, xnk, xnv,
                                     Wq, Wo, Wk, Wv, Wqh, Woh, Wkh, Wvh);
    gemm_qkv<<<384, 256, GEMM_SMEM>>>(xnq, xnk, xnv, Wqh, Wkh, Wvh,
                                      bq, bk, bv, Qh, Kh, Vh);
    attn_kernel<<<dim3(8, NQ, Bq), 256, ATTN_SMEM>>>(lens, attn);
    gemm_o<<<256, 256, GEMM_SMEM>>>(Oh, Woh, bo, out);

    // join
    cudaStreamWaitEvent(0, ev_join, 0);
}

// round 17
// speedup vs baseline: 1.0343x; 1.0343x over previous
#include <cuda_runtime.h>
#include <cuda_fp16.h>
#include <cmath>

// Problem constants
#define Bq     2
#define Sq     2048
#define Dm     1024
#define NQ     16
#define NKV    4
#define GRP    4
#define DQh    64
#define DVh    64

// exp(s*0.125) = exp2(s * C)
#define EXP2C  0.180336879f

// Scratch (device globals — no allocation allowed)
__device__ __align__(16) __half g_xnq[Bq*Sq*Dm];
__device__ __align__(16) __half g_xnk[Bq*Sq*Dm];
__device__ __align__(16) __half g_xnv[Bq*Sq*Dm];
__device__ __align__(16) __half g_Wqh[Dm*NQ*DQh];
__device__ __align__(16) __half g_Wkh[Dm*NKV*DQh];
__device__ __align__(16) __half g_Wvh[Dm*NKV*DVh];
__device__ __align__(16) __half g_Woh[NQ*DVh*Dm];
__device__ __align__(16) __half g_Qh[Bq*Sq*NQ*DQh];
__device__ __align__(16) __half g_Kh[Bq*Sq*NKV*DQh];
__device__ __align__(16) __half g_Vh[Bq*Sq*NKV*DVh];
__device__ __align__(16) __half g_Oh[Bq*Sq*NQ*DVh];

// fp16 mma: m16n8k16, f32 accum
#define MMA_F16(c, a, b0, b1)                                                  \
    asm volatile("mma.sync.aligned.m16n8k16.row.col.f32.f16.f16.f32 "          \
                 "{%0,%1,%2,%3},{%4,%5,%6,%7},{%8,%9},{%0,%1,%2,%3};"          \
                 : "+f"((c)[0]), "+f"((c)[1]), "+f"((c)[2]), "+f"((c)[3])      \
                 : "r"((a)[0]), "r"((a)[1]), "r"((a)[2]), "r"((a)[3]),         \
                   "r"(b0), "r"(b1))

__device__ __forceinline__ void ldsmx4(unsigned r[4], unsigned saddr) {
    asm volatile("ldmatrix.sync.aligned.m8n8.x4.shared.b16 {%0,%1,%2,%3}, [%4];"
                 : "=r"(r[0]), "=r"(r[1]), "=r"(r[2]), "=r"(r[3])
                 : "r"(saddr));
}
__device__ __forceinline__ void ldsmx4t(unsigned r[4], unsigned saddr) {
    asm volatile("ldmatrix.sync.aligned.m8n8.x4.trans.shared.b16 {%0,%1,%2,%3}, [%4];"
                 : "=r"(r[0]), "=r"(r[1]), "=r"(r[2]), "=r"(r[3])
                 : "r"(saddr));
}

__device__ __forceinline__ unsigned a_frag_addr(const __half* base, int lane,
                                                int r0, int ldm) {
    const __half* p = base + (size_t)(r0 + (lane & 7) + ((lane >> 3) & 1) * 8) * ldm
                           + ((lane >> 4) & 1) * 8;
    return (unsigned)__cvta_generic_to_shared(p);
}
__device__ __forceinline__ unsigned bn_frag_addr(const __half* base, int lane,
                                                 int n0, int ldm) {
    const __half* p = base + (size_t)(n0 + (lane & 7) + ((lane >> 4) & 1) * 8) * ldm
                           + ((lane >> 3) & 1) * 8;
    return (unsigned)__cvta_generic_to_shared(p);
}
__device__ __forceinline__ unsigned bt_frag_addr(const __half* base, int lane,
                                                 int k0, int n0, int ldm) {
    const __half* p = base + (size_t)(k0 + (lane & 7) + ((lane >> 3) & 1) * 8) * ldm
                           + n0 + ((lane >> 4) & 1) * 8;
    return (unsigned)__cvta_generic_to_shared(p);
}

__device__ __forceinline__ void cpasync16(unsigned dst, const void* src) {
    asm volatile("cp.async.cg.shared.global [%0], [%1], 16;" :: "r"(dst), "l"(src));
}
#define CP_COMMIT() asm volatile("cp.async.commit_group;")
#define CP_WAIT0()  asm volatile("cp.async.wait_group 0;")
#define CP_WAIT1()  asm volatile("cp.async.wait_group 1;")

__device__ __forceinline__ __half2 f22h(float a, float b) {
    return __floats2half2_rn(a, b);
}
__device__ __forceinline__ unsigned pack_h2(float a, float b) {
    __half2 h = __floats2half2_rn(a, b);
    return *(unsigned*)&h;
}
__device__ __forceinline__ __half2 h2exp2_(__half2 x) {
    __half2 y;
    asm("ex2.approx.f16x2 %0, %1;" : "=r"(*(unsigned*)&y) : "r"(*(unsigned*)&x));
    return y;
}

// ---------------------------------------------------------------------------
// Fused LayerNorm x3 + weight fp32->fp16 conversion (one launch).
// ---------------------------------------------------------------------------
__global__ void ln3w_kernel(const float* __restrict__ xq,
                            const float* __restrict__ xk,
                            const float* __restrict__ xv,
                            const float* __restrict__ gamma,
                            const float* __restrict__ beta,
                            __half* __restrict__ yq,
                            __half* __restrict__ yk,
                            __half* __restrict__ yv,
                            const float* __restrict__ Wq, const float* __restrict__ Wo,
                            const float* __restrict__ Wk, const float* __restrict__ Wv,
                            __half* wq, __half* wo, __half* wk, __half* wv)
{
    int which = blockIdx.y;
    int tid = threadIdx.x;
    if (which >= 3) {
        int w = which - 3;
        const float* src = (w == 0) ? Wq : (w == 1) ? Wo : (w == 2) ? Wk : Wv;
        __half* dst      = (w == 0) ? wq : (w == 1) ? wo : (w == 2) ? wk : wv;
        int n = (w < 2) ? Dm * Dm : Dm * NKV * DQh;
        int i = (blockIdx.x * 256 + tid) * 4;
        if (i < n) {
            float4 v = *(const float4*)&src[i];
            *(__half2*)&dst[i]     = f22h(v.x, v.y);
            *(__half2*)&dst[i + 2] = f22h(v.z, v.w);
        }
        return;
    }
    int row = blockIdx.x;
    const float* x = (which == 0) ? xq : (which == 1) ? xk : xv;
    __half* y      = (which == 0) ? yq : (which == 1) ? yk : yv;
    const float4* xr = (const float4*)(x + (size_t)row * Dm);
    float4 v = xr[tid];
    float s  = v.x + v.y + v.z + v.w;
    float ss = v.x*v.x + v.y*v.y + v.z*v.z + v.w*v.w;
    #pragma unroll
    for (int o = 16; o > 0; o >>= 1) {
        s  += __shfl_down_sync(0xffffffffu, s,  o);
        ss += __shfl_down_sync(0xffffffffu, ss, o);
    }
    __shared__ float as[8], bs[8];
    __shared__ float s_mu, s_inv;
    if ((tid & 31) == 0) { as[tid >> 5] = s; bs[tid >> 5] = ss; }
    __syncthreads();
    if (tid == 0) {
        float S = 0.f, SS = 0.f;
        #pragma unroll
        for (int i = 0; i < 8; i++) { S += as[i]; SS += bs[i]; }
        float mu  = S * (1.0f / Dm);
        float var = SS * (1.0f / Dm) - mu * mu;
        s_mu  = mu;
        s_inv = rsqrtf(var + 1e-5f);
    }
    __syncthreads();
    float mu = s_mu, inv = s_inv;
    float4 g  = ((const float4*)gamma)[tid];
    float4 bb = ((const float4*)beta )[tid];
    int base = row * Dm + tid * 4;
    *(__half2*)&y[base]     = f22h((v.x - mu) * inv * g.x + bb.x,
                                   (v.y - mu) * inv * g.y + bb.y);
    *(__half2*)&y[base + 2] = f22h((v.z - mu) * inv * g.z + bb.z,
                                   (v.w - mu) * inv * g.w + bb.w);
}

// ---------------------------------------------------------------------------
// fp16 GEMM with bias: 128x128 block, BK=32, 8 warps of 64x32, 3-stage
// cp.async pipeline, 2 CTAs/SM. Optional fused RoPE in epilogue.
// ---------------------------------------------------------------------------
#define G_ALD 40
#define G_BLD 136
#define G_AS (128*G_ALD)
#define G_BS (32*G_BLD)
#define GEMM_SMEM (3*(G_AS + G_BS)*2)

__device__ __forceinline__ void gemm_body(const __half* __restrict__ A,
                                          const __half* __restrict__ B,
                                          const float* __restrict__ bias,
                                          float* __restrict__ Cf,
                                          __half* __restrict__ Ch,
                                          int N, int K,
                                          int mblk, int nblk,
                                          bool do_rope,
                                          __half* smem)
{
    __half* As = smem;                   // [3][128][40]
    __half* Bs = smem + 3 * G_AS;        // [3][32][136]

    int tid  = threadIdx.x;
    int lane = tid & 31, wid = tid >> 5;
    int wm = (wid & 1) * 64, wn = (wid >> 1) * 32;
    int l4 = lane >> 2, lk = lane & 3;
    int mb = mblk * 128, nb = nblk * 128;

    unsigned as_base = (unsigned)__cvta_generic_to_shared(As);
    unsigned bs_base = (unsigned)__cvta_generic_to_shared(Bs);

    int ar = tid >> 1, ach = (tid & 1) * 2;
    const __half* Ap = A + (size_t)(mb + ar) * K + ach * 8;

    float c[4][4][4];
    #pragma unroll
    for (int mi = 0; mi < 4; mi++)
        #pragma unroll
        for (int nj = 0; nj < 4; nj++)
            #pragma unroll
            for (int q = 0; q < 4; q++) c[mi][nj][q] = 0.f;

    #define G_LOAD(T, BUF)                                                     \
        do {                                                                   \
            cpasync16(as_base + (unsigned)((BUF) * G_AS + ar * G_ALD + ach * 8) * 2, \
                      Ap + (size_t)(T) * 32);                                  \
            cpasync16(as_base + (unsigned)((BUF) * G_AS + ar * G_ALD + ach * 8 + 8) * 2, \
                      Ap + (size_t)(T) * 32 + 8);                              \
            _Pragma("unroll")                                                  \
            for (int u_ = 0; u_ < 2; u_++) {                                   \
                int lin_ = tid + u_ * 256;                                     \
                int kr_ = lin_ >> 4, ch_ = lin_ & 15;                          \
                cpasync16(bs_base + (unsigned)((BUF) * G_BS + kr_ * G_BLD + ch_ * 8) * 2, \
                          B + (size_t)((T) * 32 + kr_) * N + nb + ch_ * 8);    \
            }                                                                  \
        } while (0)

    int nt = K >> 5;
    G_LOAD(0, 0); CP_COMMIT();
    if (nt > 1) { G_LOAD(1, 1); CP_COMMIT(); }

    for (int t = 0; t < nt; t++) {
        int cur = t % 3;
        if (t + 1 < nt) { CP_WAIT1(); } else { CP_WAIT0(); }
        __syncthreads();
        if (t + 2 < nt) { G_LOAD(t + 2, (t + 2) % 3); CP_COMMIT(); }

        const __half* Ab = As + cur * G_AS;
        const __half* Bb = Bs + cur * G_BS;

        #pragma unroll
        for (int kk = 0; kk < 2; kk++) {
            unsigned af[4][4];
            #pragma unroll
            for (int mi = 0; mi < 4; mi++)
                ldsmx4(af[mi], a_frag_addr(Ab, lane, wm + mi * 16, G_ALD) + kk * 32);
            #pragma unroll
            for (int g = 0; g < 2; g++) {
                unsigned bfr[4];
                ldsmx4t(bfr, bt_frag_addr(Bb, lane, kk * 16, wn + g * 16, G_BLD));
                #pragma unroll
                for (int mi = 0; mi < 4; mi++) {
                    MMA_F16(c[mi][2*g],   af[mi], bfr[0], bfr[1]);
                    MMA_F16(c[mi][2*g+1], af[mi], bfr[2], bfr[3]);
                }
            }
        }
    }
    #undef G_LOAD

    #pragma unroll
    for (int nj = 0; nj < 4; nj++) {
        int col = nb + wn + nj * 8 + 2 * lk;
        float2 bj = *(const float2*)&bias[col];
        float invf = 0.f;
        if (do_rope) {
            int pi = (col & 63) >> 1;
            invf = exp2f(-0.4152410118609203f * (float)pi);
        }
        #pragma unroll
        for (int mi = 0; mi < 4; mi++) {
            int r0 = mb + wm + mi * 16 + l4;
            float v0 = c[mi][nj][0] + bj.x, v1 = c[mi][nj][1] + bj.y;
            float v2 = c[mi][nj][2] + bj.x, v3 = c[mi][nj][3] + bj.y;
            if (do_rope) {
                int t0 = r0 & (Sq - 1);
                float sn0, cs0, sn1, cs1;
                sincosf((float)t0 * invf, &sn0, &cs0);
                sincosf((float)(t0 + 8) * invf, &sn1, &cs1);
                float a0 = v0, b0 = v1;
                v0 = a0 * cs0 - b0 * sn0; v1 = a0 * sn0 + b0 * cs0;
                float a1 = v2, b1 = v3;
                v2 = a1 * cs1 - b1 * sn1; v3 = a1 * sn1 + b1 * cs1;
            }
            if (Ch) {
                *(__half2*)&Ch[(size_t)r0 * N + col] = f22h(v0, v1);
                *(__half2*)&Ch[(size_t)(r0 + 8) * N + col] = f22h(v2, v3);
            } else {
                float2 o0; o0.x = v0; o0.y = v1;
                float2 o1; o1.x = v2; o1.y = v3;
                *(float2*)&Cf[(size_t)r0 * N + col] = o0;
                *(float2*)&Cf[(size_t)(r0 + 8) * N + col] = o1;
            }
        }
    }
}

// Fused Q+K+V projections (384 GEMM CTAs, rope fused) + 512 zero-fill CTAs.
__global__ void __launch_bounds__(256, 2)
gemm_qkv(const __half* __restrict__ Aq, const __half* __restrict__ Ak,
         const __half* __restrict__ Av,
         const __half* __restrict__ Wq, const __half* __restrict__ Wk,
         const __half* __restrict__ Wv,
         const float* __restrict__ bq_, const float* __restrict__ bk_,
         const float* __restrict__ bv_,
         __half* __restrict__ Cq, __half* __restrict__ Ck,
         __half* __restrict__ Cv, float* __restrict__ attn)
{
    extern __shared__ __half smh[];
    int bx = blockIdx.x;
    if (bx < 256) {
        gemm_body(Aq, Wq, bq_, nullptr, Cq, NQ * DQh, Dm, bx >> 3, bx & 7, true, smh);
    } else if (bx < 320) {
        int i = bx - 256;
        gemm_body(Ak, Wk, bk_, nullptr, Ck, NKV * DQh, Dm, i >> 1, i & 1, true, smh);
    } else if (bx < 384) {
        int i = bx - 320;
        gemm_body(Av, Wv, bv_, nullptr, Cv, NKV * DVh, Dm, i >> 1, i & 1, false, smh);
    } else {
        int idx = bx - 384;               // 0..511
        int h = idx >> 4, mt = idx & 15;
        int c0 = 128 * (mt + 1);
        int w4 = (Sq - c0) >> 2;
        if (w4 <= 0) return;
        float4 z = make_float4(0.f, 0.f, 0.f, 0.f);
        size_t rowbase = ((size_t)h * Sq + mt * 128) * Sq + c0;
        for (int r = 0; r < 128; r++) {
            float4* rp = (float4*)(attn + rowbase + (size_t)r * Sq);
            for (int c4 = threadIdx.x; c4 < w4; c4 += 256)
                rp[c4] = z;
        }
    }
}

// Output projection: 256 CTAs
__global__ void __launch_bounds__(256, 2)
gemm_o(const __half* __restrict__ A, const __half* __restrict__ B,
       const float* __restrict__ bias, float* __restrict__ Cf)
{
    extern __shared__ __half smh[];
    int bx = blockIdx.x;
    gemm_body(A, B, bias, Cf, nullptr, Dm, Dm, bx >> 3, bx & 7, false, smh);
}

// ---------------------------------------------------------------------------
// Attention: FA2 layout, 128-wide key tiles in two halves, 2 CTAs/SM,
// complementary q-tile pairs, m-hat=0 softmax (f16x2 exp on interior tiles),
// Q frags in registers, sweep-1 K triple-buffered.
// ---------------------------------------------------------------------------
#define A_LD 72
#define A_TS (128*A_LD)
#define ATTN_SMEM (5*A_TS*2)
#define KSTEP_B (16*A_LD*2)

__global__ void __launch_bounds__(256, 2)
attn_kernel(const int* __restrict__ lens, float* __restrict__ attn)
{
    extern __shared__ __half smh[];
    __half* Qs  = smh;
    __half* Ks0 = Qs + A_TS;
    __half* Ks1 = Ks0 + A_TS;
    __half* Vs0 = Ks1 + A_TS;          // sweep 1: third K buffer
    __half* Vs1 = Vs0 + A_TS;

    int tid  = threadIdx.x;
    int lane = tid & 31, wid = tid >> 5;
    int wm = wid * 16;
    int l4 = lane >> 2, lk = lane & 3;

    int bx = blockIdx.x;                 // 0..7
    int qh = blockIdx.y, b = blockIdx.z;
    int kvh = qh >> 2;
    int grp = qh & 3;
    int len = lens[b];

    unsigned qs_addr = (unsigned)__cvta_generic_to_shared(Qs);
    unsigned ks_addr3[3] = {
        (unsigned)__cvta_generic_to_shared(Ks0),
        (unsigned)__cvta_generic_to_shared(Ks1),
        (unsigned)__cvta_generic_to_shared(Vs0)
    };
    unsigned vs_addr[2] = {
        (unsigned)__cvta_generic_to_shared(Vs0),
        (unsigned)__cvta_generic_to_shared(Vs1)
    };

    unsigned q_ptr = a_frag_addr(Qs, lane, wm, A_LD);
    unsigned k_base3[3] = { bn_frag_addr(Ks0, lane, 0, A_LD),
                            bn_frag_addr(Ks1, lane, 0, A_LD),
                            bn_frag_addr(Vs0, lane, 0, A_LD) };
    unsigned v_base[2] = { bt_frag_addr(Vs0, lane, 0, 0, A_LD),
                           bt_frag_addr(Vs1, lane, 0, 0, A_LD) };

    size_t attn_head = (((size_t)(b * GRP + grp)) * NKV + kvh) * Sq;

    #define LOAD_K_ASYNC(JT, BUFADDR)                                           \
        do {                                                                    \
            _Pragma("unroll")                                                   \
            for (int i_ = 0; i_ < 4; i_++) {                                    \
                int lin_ = tid + i_ * 256;                                      \
                int r_ = lin_ >> 3, ch_ = lin_ & 7;                             \
                cpasync16((BUFADDR) + (unsigned)(r_ * A_LD + ch_ * 8) * 2,      \
                    &g_Kh[((size_t)(b * Sq + (JT) * 128 + r_)) * (NKV * DQh)    \
                          + kvh * 64 + ch_ * 8]);                               \
            }                                                                   \
        } while (0)
    #define LOAD_V_ASYNC(JT, BUFADDR)                                           \
        do {                                                                    \
            _Pragma("unroll")                                                   \
            for (int i_ = 0; i_ < 4; i_++) {                                    \
                int lin_ = tid + i_ * 256;                                      \
                int r_ = lin_ >> 3, ch_ = lin_ & 7;                             \
                cpasync16((BUFADDR) + (unsigned)(r_ * A_LD + ch_ * 8) * 2,      \
                    &g_Vh[((size_t)(b * Sq + (JT) * 128 + r_)) * (NKV * DQh)    \
                          + kvh * 64 + ch_ * 8]);                               \
            }                                                                   \
        } while (0)

    #define QK_HALF(KB, H)                                                      \
        do {                                                                    \
            _Pragma("unroll")                                                   \
            for (int kk = 0; kk < 4; kk++) {                                    \
                _Pragma("unroll")                                               \
                for (int g2 = 0; g2 < 4; g2++) {                                \
                    unsigned bfr[4];                                            \
                    ldsmx4(bfr, (KB) + ((H) * 4 + g2) * KSTEP_B + kk * 32);     \
                    MMA_F16(s[2*g2],   qf[kk], bfr[0], bfr[1]);                 \
                    MMA_F16(s[2*g2+1], qf[kk], bfr[2], bfr[3]);                 \
                }                                                               \
            }                                                                   \
        } while (0)

    #pragma unroll 1
    for (int hp = 0; hp < 2; hp++) {
        int mt = hp ? bx : (Sq / 128 - 1 - bx);   // heavy tile first
        __syncthreads();

        int jend = min(mt, (len - 1) >> 7);

        #pragma unroll
        for (int i = 0; i < 4; i++) {
            int lin = tid + i * 256;
            int r = lin >> 3, ch = lin & 7;
            cpasync16(qs_addr + (unsigned)(r * A_LD + ch * 8) * 2,
                      &g_Qh[((size_t)(b * Sq + mt * 128 + r)) * (NQ * DQh) + qh * 64 + ch * 8]);
        }
        LOAD_K_ASYNC(0, ks_addr3[0]);
        CP_COMMIT();
        if (jend >= 1) { LOAD_K_ASYNC(1, ks_addr3[1]); CP_COMMIT(); }

        float rl0 = 0.f, rl1 = 0.f;
        int qr0 = mt * 128 + wm + l4, qr1 = qr0 + 8;

        if (jend >= 1) { CP_WAIT1(); } else { CP_WAIT0(); }
        __syncthreads();
        unsigned qf[4][4];
        #pragma unroll
        for (int kk = 0; kk < 4; kk++)
            ldsmx4(qf[kk], q_ptr + kk * 32);

        // =================== Sweep 1: l only (m-hat = 0), K 3-stage =========
        for (int jt = 0; jt <= jend; jt++) {
            int kb = jt % 3;
            if (jt > 0) {
                if (jt < jend) { CP_WAIT1(); } else { CP_WAIT0(); }
                __syncthreads();
            }
            if (jt + 2 <= jend) { LOAD_K_ASYNC(jt + 2, ks_addr3[(jt + 2) % 3]); CP_COMMIT(); }
            bool boundary = (jt == jend);

            float s0 = 0.f, s1 = 0.f;
            #pragma unroll
            for (int H = 0; H < 2; H++) {
                float s[8][4];
                #pragma unroll
                for (int nj = 0; nj < 8; nj++)
                    #pragma unroll
                    for (int q = 0; q < 4; q++) s[nj][q] = 0.f;
                QK_HALF(k_base3[kb], H);

                if (boundary) {
                    #pragma unroll
                    for (int nj = 0; nj < 8; nj++) {
                        int kc0 = jt * 128 + H * 64 + nj * 8 + 2 * lk, kc1 = kc0 + 1;
                        s0 += ((kc0 > qr0 || kc0 >= len) ? 0.f : exp2f(s[nj][0] * EXP2C))
                            + ((kc1 > qr0 || kc1 >= len) ? 0.f : exp2f(s[nj][1] * EXP2C));
                        s1 += ((kc0 > qr1 || kc0 >= len) ? 0.f : exp2f(s[nj][2] * EXP2C))
                            + ((kc1 > qr1 || kc1 >= len) ? 0.f : exp2f(s[nj][3] * EXP2C));
                    }
                } else {
                    #pragma unroll
                    for (int nj = 0; nj < 8; nj++) {
                        __half2 e01 = h2exp2_(f22h(s[nj][0] * EXP2C, s[nj][1] * EXP2C));
                        __half2 e23 = h2exp2_(f22h(s[nj][2] * EXP2C, s[nj][3] * EXP2C));
                        float2 f01 = __half22float2(e01);
                        float2 f23 = __half22float2(e23);
                        s0 += f01.x + f01.y;
                        s1 += f23.x + f23.y;
                    }
                }
            }
            s0 += __shfl_xor_sync(0xffffffffu, s0, 1);
            s0 += __shfl_xor_sync(0xffffffffu, s0, 2);
            s1 += __shfl_xor_sync(0xffffffffu, s1, 1);
            s1 += __shfl_xor_sync(0xffffffffu, s1, 2);
            rl0 += s0;
            rl1 += s1;
        }
        __syncthreads();

        float il0 = 1.0f / rl0, il1 = 1.0f / rl1;

        float o[8][4];
        #pragma unroll
        for (int dj = 0; dj < 8; dj++)
            #pragma unroll
            for (int q = 0; q < 4; q++) o[dj][q] = 0.f;

        // =================== Sweep 2: probs + PV ============================
        LOAD_K_ASYNC(0, ks_addr3[0]);
        LOAD_V_ASYNC(0, vs_addr[0]);
        CP_COMMIT();
        for (int jt = 0; jt <= jend; jt++) {
            CP_WAIT0();
            __syncthreads();
            int kb = jt & 1;
            if (jt < jend) {
                LOAD_K_ASYNC(jt + 1, ks_addr3[kb ^ 1]);
                LOAD_V_ASYNC(jt + 1, vs_addr[kb ^ 1]);
                CP_COMMIT();
            }
            bool boundary = (jt == jend);

            #pragma unroll
            for (int H = 0; H < 2; H++) {
                float s[8][4];
                #pragma unroll
                for (int nj = 0; nj < 8; nj++)
                    #pragma unroll
                    for (int q = 0; q < 4; q++) s[nj][q] = 0.f;
                QK_HALF(k_base3[kb], H);

                if (boundary) {
                    #pragma unroll
                    for (int nj = 0; nj < 8; nj++) {
                        int kc0 = jt * 128 + H * 64 + nj * 8 + 2 * lk, kc1 = kc0 + 1;
                        s[nj][0] = (kc0 > qr0 || kc0 >= len) ? 0.f
                                 : exp2f(s[nj][0] * EXP2C) * il0;
                        s[nj][1] = (kc1 > qr0 || kc1 >= len) ? 0.f
                                 : exp2f(s[nj][1] * EXP2C) * il0;
                        s[nj][2] = (kc0 > qr1 || kc0 >= len) ? 0.f
                                 : exp2f(s[nj][2] * EXP2C) * il1;
                        s[nj][3] = (kc1 > qr1 || kc1 >= len) ? 0.f
                                 : exp2f(s[nj][3] * EXP2C) * il1;
                    }
                } else {
                    #pragma unroll
                    for (int nj = 0; nj < 8; nj++) {
                        __half2 e01 = h2exp2_(f22h(s[nj][0] * EXP2C, s[nj][1] * EXP2C));
                        __half2 e23 = h2exp2_(f22h(s[nj][2] * EXP2C, s[nj][3] * EXP2C));
                        float2 f01 = __half22float2(e01);
                        float2 f23 = __half22float2(e23);
                        s[nj][0] = f01.x * il0;
                        s[nj][1] = f01.y * il0;
                        s[nj][2] = f23.x * il1;
                        s[nj][3] = f23.y * il1;
                    }
                }

                #pragma unroll
                for (int kk = 0; kk < 4; kk++) {
                    unsigned af[4];
                    af[0] = pack_h2(s[2*kk][0],   s[2*kk][1]);
                    af[1] = pack_h2(s[2*kk][2],   s[2*kk][3]);
                    af[2] = pack_h2(s[2*kk+1][0], s[2*kk+1][1]);
                    af[3] = pack_h2(s[2*kk+1][2], s[2*kk+1][3]);
                    #pragma unroll
                    for (int g = 0; g < 4; g++) {
                        unsigned bfr[4];
                        ldsmx4t(bfr, v_base[kb] + g * 32 + (H * 4 + kk) * KSTEP_B);
                        MMA_F16(o[2*g],   af, bfr[0], bfr[1]);
                        MMA_F16(o[2*g+1], af, bfr[2], bfr[3]);
                    }
                }

                #pragma unroll
                for (int nj = 0; nj < 8; nj++) {
                    int kc0 = jt * 128 + H * 64 + nj * 8 + 2 * lk;
                    float2 w0; w0.x = s[nj][0]; w0.y = s[nj][1];
                    float2 w1; w1.x = s[nj][2]; w1.y = s[nj][3];
                    *(float2*)&attn[(attn_head + qr0) * Sq + kc0] = w0;
                    *(float2*)&attn[(attn_head + qr1) * Sq + kc0] = w1;
                }
            }
        }

        // zero-fill dynamic masked band (jend+1 .. mt); static jt > mt pre-zeroed.
        for (int jt = jend + 1; jt <= mt; jt++) {
            float4 z = make_float4(0.f, 0.f, 0.f, 0.f);
            #pragma unroll
            for (int i = 0; i < 16; i++) {
                int lin = tid + i * 256;
                int r = lin >> 5, c4 = (lin & 31) * 4;
                *(float4*)&attn[(attn_head + mt * 128 + r) * Sq + jt * 128 + c4] = z;
            }
        }

        // epilogue: write O (fp16)
        {
            int gr0 = b * Sq + qr0;
            #pragma unroll
            for (int dj = 0; dj < 8; dj++) {
                int col = qh * 64 + dj * 8 + 2 * lk;
                *(__half2*)&g_Oh[(size_t)gr0 * (NQ * DVh) + col] = f22h(o[dj][0], o[dj][1]);
                *(__half2*)&g_Oh[(size_t)(gr0 + 8) * (NQ * DVh) + col] = f22h(o[dj][2], o[dj][3]);
            }
        }
    }
    #undef LOAD_K_ASYNC
    #undef LOAD_V_ASYNC
    #undef QK_HALF
}

// ---------------------------------------------------------------------------
// Launch
// ---------------------------------------------------------------------------
extern "C" void kernel_launch(void* const* d_in, const int* in_sizes, int n_in,
                              void* d_out, int out_size)
{
    const float* x_q  = (const float*)d_in[0];
    const float* x_k  = (const float*)d_in[1];
    const float* x_v  = (const float*)d_in[2];
    const int*   lens = (const int*)  d_in[3];
    const float* gam  = (const float*)d_in[4];
    const float* bet  = (const float*)d_in[5];
    const float* Wq   = (const float*)d_in[6];
    const float* bq   = (const float*)d_in[7];
    const float* Wk   = (const float*)d_in[8];
    const float* bk   = (const float*)d_in[9];
    const float* Wv   = (const float*)d_in[10];
    const float* bv   = (const float*)d_in[11];
    const float* Wo   = (const float*)d_in[12];
    const float* bo   = (const float*)d_in[13];

    float* out  = (float*)d_out;                       // (B, S, 1024)
    float* attn = out + (size_t)Bq * Sq * Dm;          // (B, GRP, NKV, S, S)

    __half *xnq, *xnk, *xnv, *Qh, *Kh, *Vh, *Oh;
    __half *Wqh, *Wkh, *Wvh, *Woh;
    cudaGetSymbolAddress((void**)&xnq, g_xnq);
    cudaGetSymbolAddress((void**)&xnk, g_xnk);
    cudaGetSymbolAddress((void**)&xnv, g_xnv);
    cudaGetSymbolAddress((void**)&Qh,  g_Qh);
    cudaGetSymbolAddress((void**)&Kh,  g_Kh);
    cudaGetSymbolAddress((void**)&Vh,  g_Vh);
    cudaGetSymbolAddress((void**)&Oh,  g_Oh);
    cudaGetSymbolAddress((void**)&Wqh, g_Wqh);
    cudaGetSymbolAddress((void**)&Wkh, g_Wkh);
    cudaGetSymbolAddress((void**)&Wvh, g_Wvh);
    cudaGetSymbolAddress((void**)&Woh, g_Woh);

    const int M = Bq * Sq;   // 4096

    static bool attr_set = false;
    if (!attr_set) {
        cudaFuncSetAttribute(gemm_qkv, cudaFuncAttributeMaxDynamicSharedMemorySize, GEMM_SMEM);
        cudaFuncSetAttribute(gemm_o, cudaFuncAttributeMaxDynamicSharedMemorySize, GEMM_SMEM);
        cudaFuncSetAttribute(attn_kernel, cudaFuncAttributeMaxDynamicSharedMemorySize, ATTN_SMEM);
        attr_set = true;
    }

    // 1) LayerNorms + weight conversion (one launch)
    ln3w_kernel<<<dim3(M, 7), 256>>>(x_q, x_k, x_v, gam, bet, xnq, xnk, xnv,
                                     Wq, Wo, Wk, Wv, Wqh, Woh, Wkh, Wvh);

    // 2) Q+K+V projections (rope fused) + static attn zero-fill, ONE launch
    gemm_qkv<<<896, 256, GEMM_SMEM>>>(xnq, xnk, xnv, Wqh, Wkh, Wvh,
                                      bq, bk, bv, Qh, Kh, Vh, attn);

    // 3) Attention (FA2, paired q-tiles, m-hat=0 softmax w/ f16x2 exp)
    attn_kernel<<<dim3(8, NQ, Bq), 256, ATTN_SMEM>>>(lens, attn);

    // 4) Output projection
    gemm_o<<<256, 256, GEMM_SMEM>>>(Oh, Woh, bo, out);
}